// round 16
// baseline (speedup 1.0000x reference)
#include <cuda_runtime.h>
#include <cstdint>

#define BATCHES 16
#define NPTS    65536
#define NSAMP   2048
#define CPB     8                  // CTAs per cluster (= per batch)
#define TPB     512
#define NWARPS  (TPB / 32)         // 16
#define PPT     16                 // points per thread
#define NPAIR   (PPT / 2)          // 8 packed pairs
#define SLAB    (NPTS / CPB)       // 8192 = TPB * PPT
#define SLAB_SHIFT 13              // log2(SLAB)

#define ADD_X2(o, a, b) asm("add.rn.f32x2 %0, %1, %2;" : "=l"(o) : "l"(a), "l"(b))
#define MUL_X2(o, a, b) asm("mul.rn.f32x2 %0, %1, %2;" : "=l"(o) : "l"(a), "l"(b))
#define FMA_X2(o, a, b, c) \
    asm("fma.rn.f32x2 %0, %1, %2, %3;" : "=l"(o) : "l"(a), "l"(b), "l"(c))
#define PACK2(o, lo, hi) asm("mov.b64 %0, {%1, %2};" : "=l"(o) : "f"(lo), "f"(hi))
#define UNPACK2(lo, hi, v) asm("mov.b64 {%0, %1}, %2;" : "=f"(lo), "=f"(hi) : "l"(v))

__device__ __forceinline__ uint32_t smem_u32(const void* p) {
    return (uint32_t)__cvta_generic_to_shared(p);
}
__device__ __forceinline__ void st_remote_v2(uint32_t laddr, uint32_t rank,
                                             uint32_t a, uint32_t b) {
    uint32_t raddr;
    asm volatile("mapa.shared::cluster.u32 %0, %1, %2;"
                 : "=r"(raddr) : "r"(laddr), "r"(rank));
    asm volatile("st.shared::cluster.v2.b32 [%0], {%1, %2};"
                 :: "r"(raddr), "r"(a), "r"(b) : "memory");
}
__device__ __forceinline__ void st_remote_v4(uint32_t laddr, uint32_t rank,
                                             float x, float y, float z, float w) {
    uint32_t raddr;
    asm volatile("mapa.shared::cluster.u32 %0, %1, %2;"
                 : "=r"(raddr) : "r"(laddr), "r"(rank));
    asm volatile("st.shared::cluster.v4.f32 [%0], {%1, %2, %3, %4};"
                 :: "r"(raddr), "f"(x), "f"(y), "f"(z), "f"(w) : "memory");
}
// release-arrive on CTA `rank`'s mbarrier (orders prior cluster-space stores)
__device__ __forceinline__ void mbar_arrive_remote(uint32_t lmbar, uint32_t rank) {
    asm volatile(
        "{\n\t"
        ".reg .b32 r;\n\t"
        "mapa.shared::cluster.u32 r, %0, %1;\n\t"
        "mbarrier.arrive.release.cluster.shared::cluster.b64 _, [r];\n\t"
        "}"
        :: "r"(lmbar), "r"(rank) : "memory");
}
__device__ __forceinline__ void mbar_wait_parity(uint32_t mbar, uint32_t parity) {
    asm volatile(
        "{\n\t"
        ".reg .pred P;\n\t"
        "WL_%=:\n\t"
        "mbarrier.try_wait.parity.acquire.cluster.shared::cta.b64 P, [%0], %1, 0x989680;\n\t"
        "@P bra.uni WD_%=;\n\t"
        "bra.uni WL_%=;\n\t"
        "WD_%=:\n\t"
        "}"
        :: "r"(mbar), "r"(parity) : "memory");
}
__device__ __forceinline__ void cluster_barrier() {
    asm volatile("barrier.cluster.arrive.aligned;" ::: "memory");
    asm volatile("barrier.cluster.wait.aligned;"   ::: "memory");
}

__global__ void __launch_bounds__(TPB, 1) __cluster_dims__(CPB, 1, 1)
fps_cluster(const float* __restrict__ points, float* __restrict__ out)
{
    const int tid  = threadIdx.x;
    const int warp = tid >> 5;
    const int lane = tid & 31;
    uint32_t rank;
    asm("mov.u32 %0, %%cluster_ctarank;" : "=r"(rank));
    const int batch = blockIdx.x / CPB;
    const float* bp = points + (size_t)batch * NPTS * 3;

    __shared__ uint2  warp_pair[NWARPS];     // {valbits, idx} per warp
    __shared__ float4 warp_xyz[NWARPS];
    __shared__ uint2  cta_pair[2][CPB];      // per-CTA results, double-buffered
    __shared__ float4 cta_xyz[2][CPB];
    __shared__ float4 s_cent;                // broadcast centroid
    __shared__ unsigned long long mbar[1];
    const uint32_t mbar_a = smem_u32(&mbar[0]);

    if (tid == 0) {
        asm volatile("mbarrier.init.shared.b64 [%0], %1;"
                     :: "r"(mbar_a), "r"(CPB) : "memory");
    }
    __syncthreads();

    // ---- packed register-resident coords + scalar min_dist ----
    unsigned long long px2[NPAIR], py2[NPAIR], pz2[NPAIR];
    float md[PPT];
    const int base = (int)rank * SLAB + tid;      // owned indices ascend with k
    #pragma unroll
    for (int j = 0; j < NPAIR; j++) {
        int i0 = base + (2 * j) * TPB;
        int i1 = base + (2 * j + 1) * TPB;
        float x0 = __ldg(bp + 3 * i0), y0 = __ldg(bp + 3 * i0 + 1), z0 = __ldg(bp + 3 * i0 + 2);
        float x1 = __ldg(bp + 3 * i1), y1 = __ldg(bp + 3 * i1 + 1), z1 = __ldg(bp + 3 * i1 + 2);
        PACK2(px2[j], x0, x1);
        PACK2(py2[j], y0, y1);
        PACK2(pz2[j], z0, z1);
        md[2 * j] = 1e10f;
        md[2 * j + 1] = 1e10f;
    }

    float cx = __ldg(bp), cy = __ldg(bp + 1), cz = __ldg(bp + 2);
    if (rank == 0 && tid == 0) out[batch * NSAMP] = 0.0f;

    cluster_barrier();   // mbarriers initialized cluster-wide; CTAs resident

    for (int m = 1; m < NSAMP; m++) {
        // ---- packed distance update; bit-exact to validated scalar form ----
        unsigned long long c2x, c2y, c2z;
        {
            float nx = -cx, ny = -cy, nz = -cz;
            PACK2(c2x, nx, nx); PACK2(c2y, ny, ny); PACK2(c2z, nz, nz);
        }
        float vbest = -1.0f;
        int bk = 0;
        float wx = 0.0f, wy = 0.0f, wz = 0.0f;
        #pragma unroll
        for (int j = 0; j < NPAIR; j++) {
            unsigned long long dx2, dy2, dz2, t;
            ADD_X2(dx2, px2[j], c2x);
            ADD_X2(dy2, py2[j], c2y);
            ADD_X2(dz2, pz2[j], c2z);
            MUL_X2(t, dx2, dx2);
            FMA_X2(t, dy2, dy2, t);
            FMA_X2(t, dz2, dz2, t);
            float d0, d1;
            UNPACK2(d0, d1, t);
            float x0, x1, y0, y1, z0, z1;
            UNPACK2(x0, x1, px2[j]);         // register-pair decomposition
            UNPACK2(y0, y1, py2[j]);
            UNPACK2(z0, z1, pz2[j]);
            // inline first-occurrence argmax (strict > keeps earliest k;
            // k ascends, owned global idx = base + k*TPB ascends with k)
            float n0 = fminf(md[2 * j], d0);
            md[2 * j] = n0;
            if (n0 > vbest) { vbest = n0; bk = 2 * j; wx = x0; wy = y0; wz = z0; }
            float n1 = fminf(md[2 * j + 1], d1);
            md[2 * j + 1] = n1;
            if (n1 > vbest) { vbest = n1; bk = 2 * j + 1; wx = x1; wy = y1; wz = z1; }
        }
        const uint32_t bi = (uint32_t)(base + bk * TPB);

        // ---- warp argmax via REDUX (md >= 0 => u32 order == float order) ----
        const uint32_t vbits = __float_as_uint(vbest);
        const uint32_t wv = __reduce_max_sync(0xffffffffu, vbits);
        const uint32_t wi = __reduce_min_sync(0xffffffffu,
                                (vbits == wv) ? bi : 0xffffffffu);
        if (bi == wi) {                        // exactly one lane (indices unique)
            warp_pair[warp] = make_uint2(wv, wi);
            warp_xyz[warp]  = make_float4(wx, wy, wz, 0.0f);  // coords already here
        }
        __syncthreads();

        // ---- warp0: block reduce, DSMEM delivery, wait, final reduce ----
        if (warp == 0) {
            uint2 p = warp_pair[lane & (NWARPS - 1)];   // dups harmless
            const uint32_t bv  = __reduce_max_sync(0xffffffffu, p.x);
            const uint32_t bix = __reduce_min_sync(0xffffffffu,
                                    (p.x == bv) ? p.y : 0xffffffffu);
            if (lane < CPB) {
                const int wwarp = (int)((bix & (TPB - 1)) >> 5);  // winner's warp
                float4 t = warp_xyz[wwarp];                       // uniform LDS
                st_remote_v2(smem_u32(&cta_pair[m & 1][rank]), (uint32_t)lane,
                             bv, bix);
                st_remote_v4(smem_u32(&cta_xyz[m & 1][rank]), (uint32_t)lane,
                             t.x, t.y, t.z, 0.0f);
                mbar_arrive_remote(mbar_a, (uint32_t)lane);   // release: orders stores
            }
            // only warp0 waits (TRYWAIT sleep), others idle at bar.sync below
            mbar_wait_parity(mbar_a, (uint32_t)((m - 1) & 1));

            uint2 q = cta_pair[m & 1][lane & (CPB - 1)];
            const uint32_t gv = __reduce_max_sync(0xffffffffu, q.x);
            const uint32_t gi = __reduce_min_sync(0xffffffffu,
                                    (q.x == gv) ? q.y : 0xffffffffu);
            const int widx = (int)gi;
            const int wr   = widx >> SLAB_SHIFT;        // winning rank (slab owner)
            float4 c = cta_xyz[m & 1][wr];              // uniform LDS
            if (lane == 0) {
                s_cent = c;
                if (rank == 0) out[batch * NSAMP + m] = (float)widx;
            }
        }
        __syncthreads();   // drains warp0's STS; broadcasts centroid

        float4 c = s_cent;
        cx = c.x; cy = c.y; cz = c.z;
        // slot-reuse safety: writing cta_*[(m+2)&1] requires warp0 passing
        // wait(m+1), which needs every CTA's m+1 arrival, which follows their
        // m reads. warp_pair/warp_xyz reuse separated by the two bar.syncs.
        // Early-phase-flip impossible: any m+1 arrival trails all m arrivals
        // by >= one full compute iteration (>=1500 cyc) vs <=240 cyc DSMEM flight.
    }
}

extern "C" void kernel_launch(void* const* d_in, const int* in_sizes, int n_in,
                              void* d_out, int out_size) {
    const float* points = (const float*)d_in[0];
    float* out = (float*)d_out;

    cudaLaunchConfig_t cfg = {};
    cfg.gridDim  = dim3(BATCHES * CPB, 1, 1);
    cfg.blockDim = dim3(TPB, 1, 1);
    cfg.dynamicSmemBytes = 0;
    cfg.stream = 0;

    cudaLaunchAttribute attrs[1];
    attrs[0].id = cudaLaunchAttributeClusterDimension;
    attrs[0].val.clusterDim.x = CPB;
    attrs[0].val.clusterDim.y = 1;
    attrs[0].val.clusterDim.z = 1;
    cfg.attrs = attrs;
    cfg.numAttrs = 1;

    cudaLaunchKernelEx(&cfg, fps_cluster, points, out);
}

// round 17
// speedup vs baseline: 1.3419x; 1.3419x over previous
#include <cuda_runtime.h>
#include <cstdint>

#define BATCHES 16
#define NPTS    65536
#define NSAMP   2048
#define CPB     8                  // CTAs per cluster (= per batch)
#define TPB     512
#define NWARPS  (TPB / 32)         // 16
#define PPT     16                 // points per thread
#define NPAIR   (PPT / 2)          // 8 packed pairs
#define SLAB    (NPTS / CPB)       // 8192 = TPB * PPT
#define SLAB_SHIFT 13              // log2(SLAB)

// dynamic smem layout (bytes)
#define SM_X     0                 // float[SLAB]
#define SM_Y     (SLAB * 4)        // float[SLAB]
#define SM_Z     (SLAB * 8)        // float[SLAB]
#define SM_WP    (SLAB * 12)                    // uint2[NWARPS]
#define SM_CP    (SM_WP + NWARPS * 8)           // uint2[2][CPB]
#define SM_CX    (SM_CP + 2 * CPB * 8)          // float4[2][CPB]
#define SM_TOTAL (SM_CX + 2 * CPB * 16)

#define ADD_X2(o, a, b) asm("add.rn.f32x2 %0, %1, %2;" : "=l"(o) : "l"(a), "l"(b))
#define MUL_X2(o, a, b) asm("mul.rn.f32x2 %0, %1, %2;" : "=l"(o) : "l"(a), "l"(b))
#define FMA_X2(o, a, b, c) \
    asm("fma.rn.f32x2 %0, %1, %2, %3;" : "=l"(o) : "l"(a), "l"(b), "l"(c))
#define PACK2(o, lo, hi) asm("mov.b64 %0, {%1, %2};" : "=l"(o) : "f"(lo), "f"(hi))
#define UNPACK2(lo, hi, v) asm("mov.b64 {%0, %1}, %2;" : "=f"(lo), "=f"(hi) : "l"(v))

__device__ __forceinline__ uint32_t smem_u32(const void* p) {
    return (uint32_t)__cvta_generic_to_shared(p);
}
__device__ __forceinline__ void st_remote_v2(uint32_t laddr, uint32_t rank,
                                             uint32_t a, uint32_t b) {
    uint32_t raddr;
    asm volatile("mapa.shared::cluster.u32 %0, %1, %2;"
                 : "=r"(raddr) : "r"(laddr), "r"(rank));
    asm volatile("st.shared::cluster.v2.b32 [%0], {%1, %2};"
                 :: "r"(raddr), "r"(a), "r"(b) : "memory");
}
__device__ __forceinline__ void st_remote_v4(uint32_t laddr, uint32_t rank,
                                             float x, float y, float z, float w) {
    uint32_t raddr;
    asm volatile("mapa.shared::cluster.u32 %0, %1, %2;"
                 : "=r"(raddr) : "r"(laddr), "r"(rank));
    asm volatile("st.shared::cluster.v4.f32 [%0], {%1, %2, %3, %4};"
                 :: "r"(raddr), "f"(x), "f"(y), "f"(z), "f"(w) : "memory");
}
__device__ __forceinline__ void cluster_barrier() {
    asm volatile("barrier.cluster.arrive.aligned;" ::: "memory");
    asm volatile("barrier.cluster.wait.aligned;"   ::: "memory");
}

__global__ void __launch_bounds__(TPB, 1) __cluster_dims__(CPB, 1, 1)
fps_cluster(const float* __restrict__ points, float* __restrict__ out)
{
    extern __shared__ char smem[];
    float* sx = (float*)(smem + SM_X);
    float* sy = (float*)(smem + SM_Y);
    float* sz = (float*)(smem + SM_Z);
    uint2*  warp_pair = (uint2*)(smem + SM_WP);
    uint2*  cta_pair  = (uint2*)(smem + SM_CP);   // [2][CPB] flattened
    float4* cta_xyz   = (float4*)(smem + SM_CX);  // [2][CPB] flattened

    const int tid  = threadIdx.x;
    const int warp = tid >> 5;
    const int lane = tid & 31;
    uint32_t rank;
    asm("mov.u32 %0, %%cluster_ctarank;" : "=r"(rank));
    const int batch = blockIdx.x / CPB;
    const float* bp = points + (size_t)batch * NPTS * 3;

    // ---- packed register-resident coords + smem coord table + min_dist ----
    unsigned long long px2[NPAIR], py2[NPAIR], pz2[NPAIR];
    float md[PPT];
    const int base = (int)rank * SLAB + tid;      // owned indices ascend with k
    #pragma unroll
    for (int j = 0; j < NPAIR; j++) {
        int i0 = base + (2 * j) * TPB;
        int i1 = base + (2 * j + 1) * TPB;
        float x0 = __ldg(bp + 3 * i0), y0 = __ldg(bp + 3 * i0 + 1), z0 = __ldg(bp + 3 * i0 + 2);
        float x1 = __ldg(bp + 3 * i1), y1 = __ldg(bp + 3 * i1 + 1), z1 = __ldg(bp + 3 * i1 + 2);
        PACK2(px2[j], x0, x1);
        PACK2(py2[j], y0, y1);
        PACK2(pz2[j], z0, z1);
        int l0 = tid + (2 * j) * TPB, l1 = tid + (2 * j + 1) * TPB;
        sx[l0] = x0; sy[l0] = y0; sz[l0] = z0;    // CTA-local coord table
        sx[l1] = x1; sy[l1] = y1; sz[l1] = z1;
        md[2 * j] = 1e10f;
        md[2 * j + 1] = 1e10f;
    }

    float cx = __ldg(bp), cy = __ldg(bp + 1), cz = __ldg(bp + 2);
    if (rank == 0 && tid == 0) out[batch * NSAMP] = 0.0f;

    cluster_barrier();   // CTAs resident; coord tables visible (BAR drains STS)

    for (int m = 1; m < NSAMP; m++) {
        // ---- packed distance update; bit-exact to validated scalar form ----
        unsigned long long c2x, c2y, c2z;
        {
            float nx = -cx, ny = -cy, nz = -cz;
            PACK2(c2x, nx, nx); PACK2(c2y, ny, ny); PACK2(c2z, nz, nz);
        }
        float vbest = -1.0f;
        #pragma unroll
        for (int j = 0; j < NPAIR; j++) {
            unsigned long long dx2, dy2, dz2, t;
            ADD_X2(dx2, px2[j], c2x);
            ADD_X2(dy2, py2[j], c2y);
            ADD_X2(dz2, pz2[j], c2z);
            MUL_X2(t, dx2, dx2);
            FMA_X2(t, dy2, dy2, t);
            FMA_X2(t, dz2, dz2, t);
            float d0, d1;
            UNPACK2(d0, d1, t);
            float n0 = fminf(md[2 * j], d0);     md[2 * j] = n0;
            float n1 = fminf(md[2 * j + 1], d1); md[2 * j + 1] = n1;
            vbest = fmaxf(vbest, n0);
            vbest = fmaxf(vbest, n1);
        }
        // index-only first-occurrence rescan (descending -> smallest k)
        int bk = 0;
        #pragma unroll
        for (int k = PPT - 1; k >= 0; k--)
            if (md[k] == vbest) bk = k;
        const uint32_t bi = (uint32_t)(base + bk * TPB);

        // ---- warp argmax via REDUX (md >= 0 => u32 order == float order) ----
        const uint32_t vbits = __float_as_uint(vbest);
        const uint32_t wv = __reduce_max_sync(0xffffffffu, vbits);
        const uint32_t wi = __reduce_min_sync(0xffffffffu,
                                (vbits == wv) ? bi : 0xffffffffu);
        if (bi == wi)                          // exactly one lane (indices unique)
            warp_pair[warp] = make_uint2(wv, wi);
        __syncthreads();

        // ---- block argmax (warp 0); coords from table; DSMEM delivery ----
        if (warp == 0) {
            uint2 p = warp_pair[lane & (NWARPS - 1)];   // dups harmless
            const uint32_t bv  = __reduce_max_sync(0xffffffffu, p.x);
            const uint32_t bix = __reduce_min_sync(0xffffffffu,
                                    (p.x == bv) ? p.y : 0xffffffffu);
            if (lane < CPB) {
                const int li = (int)(bix & (SLAB - 1));   // CTA-local offset
                float X = sx[li], Y = sy[li], Z = sz[li]; // uniform LDS broadcast
                st_remote_v2(smem_u32(&cta_pair[(m & 1) * CPB + rank]),
                             (uint32_t)lane, bv, bix);
                st_remote_v4(smem_u32(&cta_xyz[(m & 1) * CPB + rank]),
                             (uint32_t)lane, X, Y, Z, 0.0f);
            }
        }

        // HW release/acquire across the cluster (best-measured sync)
        cluster_barrier();

        // ---- cluster argmax: 8 B LDS/thread + 2 REDUX ----
        uint2 q = cta_pair[(m & 1) * CPB + (lane & (CPB - 1))];
        const uint32_t gv = __reduce_max_sync(0xffffffffu, q.x);
        const uint32_t gi = __reduce_min_sync(0xffffffffu,
                                (q.x == gv) ? q.y : 0xffffffffu);
        const int widx = (int)gi;
        const int wr   = widx >> SLAB_SHIFT;         // winning rank (slab owner)
        float4 c = cta_xyz[(m & 1) * CPB + wr];      // uniform LDS broadcast
        cx = c.x; cy = c.y; cz = c.z;

        if (rank == 0 && tid == 0) out[batch * NSAMP + m] = (float)widx;
        // warp_pair reuse (m+1): separated by this iteration's cluster barrier
        // (all threads pass it after warp0's reads). cta_* slot reuse (m+2)
        // separated by the m+1 cluster barrier (transitive, as validated).
    }
}

extern "C" void kernel_launch(void* const* d_in, const int* in_sizes, int n_in,
                              void* d_out, int out_size) {
    const float* points = (const float*)d_in[0];
    float* out = (float*)d_out;

    cudaFuncSetAttribute(fps_cluster,
                         cudaFuncAttributeMaxDynamicSharedMemorySize, SM_TOTAL);

    cudaLaunchConfig_t cfg = {};
    cfg.gridDim  = dim3(BATCHES * CPB, 1, 1);
    cfg.blockDim = dim3(TPB, 1, 1);
    cfg.dynamicSmemBytes = SM_TOTAL;
    cfg.stream = 0;

    cudaLaunchAttribute attrs[1];
    attrs[0].id = cudaLaunchAttributeClusterDimension;
    attrs[0].val.clusterDim.x = CPB;
    attrs[0].val.clusterDim.y = 1;
    attrs[0].val.clusterDim.z = 1;
    cfg.attrs = attrs;
    cfg.numAttrs = 1;

    cudaLaunchKernelEx(&cfg, fps_cluster, points, out);
}